// round 6
// baseline (speedup 1.0000x reference)
#include <cuda_runtime.h>
#include <cuda_bf16.h>
#include <cstdint>

// upfirdn2d: up=(2,2), down=(1,1), pad=((2,1),(2,1)), 4x4 kernel, gain*up0*up1 = 4
// x: (16, 64, 128, 128) f32  -> out: (16, 64, 255, 255) f32
//
// R5 ncu: issue 80% / DRAM 51% -> issue-bound. This round: float4 granularity.
// One warp = one full input row (32 lanes x 4 cols). LDG.128 loads, no edge
// loads (warp edge == image edge -> zero pad), 2 shuffles per row serve 4
// columns, 8 contiguous outputs per thread per output row.
//
// Store alignment: float offset of out[i][j0] = img*65025 + i*255 + j0,
// j0 = 8*lane (even). Pair (j0,j0+1) is 8B-aligned iff (img + i) even.
// i0 = 2r even -> even output rows are "typeA" iff img even. typeB rows use
// shifted pairs (j0-1,j0): {shfl_up(o7), o0}, plus interior pairs at odd offs.

namespace {

constexpr int H = 128;
constexpr int W = 128;
constexpr int OH = 255;
constexpr int OW = 255;
constexpr int RPT = 4;            // input rows per thread strip
constexpr int NROWS = RPT + 2;

__device__ __forceinline__ void stcs2(float* p, float a, float b) {
    asm volatile("st.global.cs.v2.f32 [%0], {%1, %2};"
                 :: "l"(p), "f"(a), "f"(b) : "memory");
}
__device__ __forceinline__ void stcs1(float* p, float a) {
    asm volatile("st.global.cs.f32 [%0], %1;" :: "l"(p), "f"(a) : "memory");
}

}  // namespace

__constant__ float cK[16];

namespace {

// 8 outputs of one output row from input rows A (kernel-row ra) and B (rb):
//   o[2t]   = Kra3*A[t-1] + Kra1*A[t]   + Krb3*B[t-1] + Krb1*B[t]
//   o[2t+1] = Kra2*A[t]   + Kra0*A[t+1] + Krb2*B[t]   + Krb0*B[t+1]
template <int RA, int RB>
__device__ __forceinline__ void compute8(float o[8],
                                         const float4& A, float aL, float aR,
                                         const float4& B, float bL, float bR) {
    const float a[6] = {aL, A.x, A.y, A.z, A.w, aR};
    const float b[6] = {bL, B.x, B.y, B.z, B.w, bR};
#pragma unroll
    for (int t = 0; t < 4; t++) {
        o[2*t]   = 4.0f * (cK[RA*4+3]*a[t]   + cK[RA*4+1]*a[t+1] +
                           cK[RB*4+3]*b[t]   + cK[RB*4+1]*b[t+1]);
        o[2*t+1] = 4.0f * (cK[RA*4+2]*a[t+1] + cK[RA*4+0]*a[t+2] +
                           cK[RB*4+2]*b[t+1] + cK[RB*4+0]*b[t+2]);
    }
}

// Store 8 contiguous outputs at row+j0 (j0 = 8*lane).
__device__ __forceinline__ void store8(float* __restrict__ row, int j0,
                                       const float o[8], bool typeA, int lane) {
    if (typeA) {
        stcs2(row + j0,     o[0], o[1]);
        stcs2(row + j0 + 2, o[2], o[3]);
        stcs2(row + j0 + 4, o[4], o[5]);
        if (lane < 31) stcs2(row + j0 + 6, o[6], o[7]);  // lane31 col 255 OOB
        else           stcs1(row + j0 + 6, o[6]);
    } else {
        const float pn = __shfl_up_sync(0xffffffffu, o[7], 1);
        if (lane > 0) stcs2(row + j0 - 1, pn, o[0]);     // {prev.o7, o0}
        else          stcs1(row + j0, o[0]);
        stcs2(row + j0 + 1, o[1], o[2]);
        stcs2(row + j0 + 3, o[3], o[4]);
        stcs2(row + j0 + 5, o[5], o[6]);
        // o[7]: lanes<31 -> written by next lane's shifted pair; lane31 OOB.
    }
}

__global__ __launch_bounds__(256) void upfirdn_up2_kernel(
        const float* __restrict__ x, float* __restrict__ out) {
    const int lane = threadIdx.x;                                   // 0..31
    const int c0 = lane * 4;                                        // input col
    const int r0 = (blockIdx.y * blockDim.y + threadIdx.y) * RPT;
    const int img = blockIdx.z;

    const float* __restrict__ xp = x + (size_t)img * (H * W);
    float* __restrict__ op = out + (size_t)img * (OH * OW);
    const bool evenA = (img & 1) == 0;

    // Phase 1: batch all LDG.128 loads (high MLP).
    float4 M[NROWS];
#pragma unroll
    for (int i = 0; i < NROWS; i++) {
        const int rr = r0 - 1 + i;
        M[i] = (rr >= 0 && rr < H)
                   ? *reinterpret_cast<const float4*>(xp + (size_t)rr * W + c0)
                   : make_float4(0.f, 0.f, 0.f, 0.f);
    }

    // Phase 2: column halos via shuffles (image edge == warp edge -> zero).
    float Lh[NROWS], Rh[NROWS];
#pragma unroll
    for (int i = 0; i < NROWS; i++) {
        const float l = __shfl_up_sync(0xffffffffu, M[i].w, 1);
        const float r = __shfl_down_sync(0xffffffffu, M[i].x, 1);
        Lh[i] = (lane == 0) ? 0.0f : l;
        Rh[i] = (lane == 31) ? 0.0f : r;
    }

    // Phase 3: compute + store.
    const int j0 = 8 * lane;
#pragma unroll
    for (int k = 0; k < RPT; k++) {
        const int r = r0 + k;
        float oe[8], oo[8];
        compute8<3, 1>(oe, M[k],     Lh[k],     Rh[k],
                           M[k + 1], Lh[k + 1], Rh[k + 1]);
        compute8<2, 0>(oo, M[k + 1], Lh[k + 1], Rh[k + 1],
                           M[k + 2], Lh[k + 2], Rh[k + 2]);
        const int i0 = 2 * r;
        store8(op + (size_t)i0 * OW, j0, oe, evenA, lane);
        if (i0 + 1 < OH) {
            store8(op + (size_t)(i0 + 1) * OW, j0, oo, !evenA, lane);
        }
    }
}

}  // namespace

extern "C" void kernel_launch(void* const* d_in, const int* in_sizes, int n_in,
                              void* d_out, int out_size) {
    const float* x = (const float*)d_in[0];      // 16*64*128*128
    const float* kern = (const float*)d_in[1];   // 4*4
    float* out = (float*)d_out;                  // 16*64*255*255

    (void)in_sizes; (void)n_in; (void)out_size;

    cudaMemcpyToSymbolAsync(cK, kern, 16 * sizeof(float), 0,
                            cudaMemcpyDeviceToDevice);

    dim3 block(32, 8, 1);
    dim3 grid(1, H / (8 * RPT), 16 * 64);   // (1, 4, 1024) = 4096 blocks
    upfirdn_up2_kernel<<<grid, block>>>(x, out);
}

// round 7
// speedup vs baseline: 2.6272x; 2.6272x over previous
#include <cuda_runtime.h>
#include <cuda_bf16.h>
#include <cstdint>

// upfirdn2d: up=(2,2), down=(1,1), pad=((2,1),(2,1)), 4x4 kernel, gain*up0*up1 = 4
// x: (16, 64, 128, 128) f32  -> out: (16, 64, 255, 255) f32
//
// R6 post-mortem: per-thread-contiguous outputs -> stride-32B STG = 8 wf/store,
// 170us. Reverted to R5's interleaved layout (lane -> 2 output cols, dense
// STG.64). R5 was issue-bound (80%): in-loop LDC reloads of cK (sm_103a has no
// cbank operands), per-iter addressing, boundary predicates. This round:
//  - coefficients pre-scaled (x4) by prep kernel, copied to __constant__,
//    loaded ONCE into 16 registers
//  - uniform first/last-strip branches hoisted out of the row loop,
//    incremental row pointers, hoisted store predicates
// Store alignment: float offset of out[i][j] = img*65025 + i*255 + j; pair
// (j0,j0+1), j0 even, is 8B-aligned iff (img+i) even -> per-row typeA/typeB.

namespace {

constexpr int H = 128;
constexpr int W = 128;
constexpr int OH = 255;
constexpr int OW = 255;
constexpr int RPT = 4;             // input rows per thread strip
constexpr int NROWS = RPT + 2;

__device__ __forceinline__ void stcs2(float* p, float a, float b) {
    asm volatile("st.global.cs.v2.f32 [%0], {%1, %2};"
                 :: "l"(p), "f"(a), "f"(b) : "memory");
}
__device__ __forceinline__ void stcs1(float* p, float a) {
    asm volatile("st.global.cs.f32 [%0], %1;" :: "l"(p), "f"(a) : "memory");
}

}  // namespace

__constant__ float cK[16];
__device__ float gK[16];

namespace {

__global__ void prescale_kernel(const float* __restrict__ kern) {
    if (threadIdx.x < 16) gK[threadIdx.x] = 4.0f * kern[threadIdx.x];
}

// Store one output row's pair (a at j0, b at j0+1) for the whole warp.
// typeA: (j0,j0+1) 8B-aligned -> dense STG.64 (stride 8B across warp).
// typeB: (j0+1,j0+2) aligned -> lane0 scalar a; lanes<31 pair {b, a_next};
//        lane31 scalar b (next warp/block's lane0 covers j0+2).
__device__ __forceinline__ void store_row(float* __restrict__ rowp /*at j0*/,
                                          float a, float b, bool typeA,
                                          bool isL, bool isR, bool tail) {
    const float an = __shfl_down_sync(0xffffffffu, a, 1);
    if (typeA) {
        if (!tail) stcs2(rowp, a, b);
        else       stcs1(rowp, a);
    } else {
        if (isL) stcs1(rowp, a);
        if (!isR)      stcs2(rowp + 1, b, an);
        else if (!tail) stcs1(rowp + 1, b);
    }
}

__global__ __launch_bounds__(256) void upfirdn_up2_kernel(
        const float* __restrict__ x, float* __restrict__ out) {
    const int lane = threadIdx.x;                                   // 0..31
    const int c = blockIdx.x * 32 + lane;                           // input col
    const int strip = blockIdx.y * blockDim.y + threadIdx.y;        // 0..31
    const int r0 = strip * RPT;
    const int img = blockIdx.z;

    const float* __restrict__ xp = x + (size_t)img * (H * W);
    float* __restrict__ op = out + (size_t)img * (OH * OW);
    const bool evenA = (img & 1) == 0;  // even output rows typeA iff img even

    // Pre-scaled coefficients -> registers (one LDC batch, no in-loop LDC).
    float k[16];
#pragma unroll
    for (int i = 0; i < 16; i++) k[i] = cK[i];

    // Edge-column setup (computed once).
    const bool isL = (lane == 0), isR = (lane == 31);
    const int ecol = isL ? c - 1 : c + 1;
    const bool eOK = (isL && c > 0) || (isR && c + 1 < W);
    const bool first = (r0 == 0), last = (r0 + RPT == H);  // warp-uniform

    // ---- Phase 1: batch loads (high MLP), incremental row pointer ----
    float M[NROWS], E[NROWS];
    const float* rp = xp + (ptrdiff_t)(r0 - 1) * W;
    if (!first) { M[0] = rp[c]; E[0] = eOK ? rp[ecol] : 0.0f; }
    else        { M[0] = 0.0f;  E[0] = 0.0f; }
    rp += W;
#pragma unroll
    for (int i = 1; i <= RPT; i++) {
        M[i] = rp[c];
        E[i] = eOK ? rp[ecol] : 0.0f;
        rp += W;
    }
    if (!last) { M[RPT + 1] = rp[c]; E[RPT + 1] = eOK ? rp[ecol] : 0.0f; }
    else       { M[RPT + 1] = 0.0f;  E[RPT + 1] = 0.0f; }

    // ---- Phase 2: column halos via shuffles ----
    float L[NROWS], R[NROWS];
#pragma unroll
    for (int i = 0; i < NROWS; i++) {
        const float l = __shfl_up_sync(0xffffffffu, M[i], 1);
        const float r = __shfl_down_sync(0xffffffffu, M[i], 1);
        L[i] = isL ? E[i] : l;
        R[i] = isR ? E[i] : r;
    }

    // ---- Phase 3: compute + store, walking output pointer ----
    const int j0 = 2 * c;
    const bool tail = (c == W - 1);  // j0 = 254
    float* pe = op + (size_t)(2 * r0) * OW + j0;
#pragma unroll
    for (int kk = 0; kk < RPT; kk++) {
        const float o00 = k[15]*L[kk]   + k[13]*M[kk]   + k[7]*L[kk+1] + k[5]*M[kk+1];
        const float o01 = k[14]*M[kk]   + k[12]*R[kk]   + k[6]*M[kk+1] + k[4]*R[kk+1];
        const float o10 = k[11]*L[kk+1] + k[9] *M[kk+1] + k[3]*L[kk+2] + k[1]*M[kk+2];
        const float o11 = k[10]*M[kk+1] + k[8] *R[kk+1] + k[2]*M[kk+2] + k[0]*R[kk+2];

        store_row(pe, o00, o01, evenA, isL, isR, tail);
        if (!last || kk < RPT - 1) {  // last strip's final odd row (255) is OOB
            store_row(pe + OW, o10, o11, !evenA, isL, isR, tail);
        }
        pe += 2 * OW;
    }
}

}  // namespace

extern "C" void kernel_launch(void* const* d_in, const int* in_sizes, int n_in,
                              void* d_out, int out_size) {
    const float* x = (const float*)d_in[0];      // 16*64*128*128
    const float* kern = (const float*)d_in[1];   // 4*4
    float* out = (float*)d_out;                  // 16*64*255*255

    (void)in_sizes; (void)n_in; (void)out_size;

    // Pre-scale coefficients on device, then D2D copy into constant memory.
    prescale_kernel<<<1, 32>>>(kern);
    void* gk_addr = nullptr;
    cudaGetSymbolAddress(&gk_addr, gK);
    cudaMemcpyToSymbolAsync(cK, gk_addr, 16 * sizeof(float), 0,
                            cudaMemcpyDeviceToDevice);

    dim3 block(32, 8, 1);
    dim3 grid(W / 32, H / (8 * RPT), 16 * 64);   // (4, 4, 1024) = 16384 blocks
    upfirdn_up2_kernel<<<grid, block>>>(x, out);
}